// round 10
// baseline (speedup 1.0000x reference)
#include <cuda_runtime.h>
#include <cuda_bf16.h>

// ---------------------------------------------------------------------------
// ASLRNN3 sm_100a.
//  * only last frame feeds outs[-1]
//  * hidden recurrence: affine, i2h-independent -> homogeneous 501x501 power
//    (512-pad). ENTIRE chain (pad + 5 squarings + hidden GEMM) in ONE
//    persistent 64-block kernel with a software grid barrier, run ALONE
//    (single stream, sequential) so the barrier never straggles on
//    SM contention (R6's mistake was overlapping it with the front-end).
//  * all GEMMs: bf16 hi/lo split 3-MMA, fp32 accum, cp.async (16B = L2-only,
//    so cross-phase global coherence holds with threadfence + barrier).
// ---------------------------------------------------------------------------

#define NB 512
#define FEAT 304
#define HF 300
#define YK 9504
#define HID 500
#define HIDP 512
#define OUT 10
#define L2S 11         // l2 split-K  (9504 = 11*864, 864 = 27*32)
#define L2LEN 864
#define CHB 64         // chain grid (8x8 tiles), < #SMs -> co-resident alone

typedef __nv_bfloat16 bf;

// ---- scratch ----
__device__ bf g_feath[1024 * FEAT];
__device__ bf g_featl[1024 * FEAT];
__device__ float g_both[1024 * HF];
__device__ bf g_yh[NB * YK];
__device__ bf g_yl[NB * YK];
__device__ float g_part[L2S * NB * HID];
__device__ bf g_Wh [HIDP * HIDP];
__device__ bf g_Wl [HIDP * HIDP];
__device__ bf g_WTh[HIDP * HIDP];
__device__ bf g_WTl[HIDP * HIDP];
__device__ bf g_M0h[HIDP * HIDP];
__device__ bf g_M0l[HIDP * HIDP];
__device__ bf g_M0Th[HIDP * HIDP];
__device__ bf g_M0Tl[HIDP * HIDP];
__device__ bf g_M1h[HIDP * HIDP];
__device__ bf g_M1l[HIDP * HIDP];
__device__ bf g_M1Th[HIDP * HIDP];
__device__ bf g_M1Tl[HIDP * HIDP];
__device__ bf g_h0h[NB * HIDP];
__device__ bf g_h0l[NB * HIDP];
__device__ float g_hid[NB * HID];

// software grid barrier state
__device__ unsigned g_cnt = 0;
__device__ volatile unsigned g_gen = 0;

#define MMA16816(c, a, b) asm volatile( \
    "mma.sync.aligned.m16n8k16.row.col.f32.bf16.bf16.f32 " \
    "{%0,%1,%2,%3},{%4,%5,%6,%7},{%8,%9},{%0,%1,%2,%3};\n" \
    : "+f"((c)[0]), "+f"((c)[1]), "+f"((c)[2]), "+f"((c)[3]) \
    : "r"((a)[0]), "r"((a)[1]), "r"((a)[2]), "r"((a)[3]), \
      "r"((b)[0]), "r"((b)[1]))

__device__ __forceinline__ unsigned ld32bf(const bf* p) {
    return *reinterpret_cast<const unsigned*>(p);
}
__device__ __forceinline__ void split_pair(float x, bf& h, bf& l) {
    h = __float2bfloat16(x);
    l = __float2bfloat16(x - __bfloat162float(h));
}
__device__ __forceinline__ void cp16(unsigned dst, const void* src) {
    asm volatile("cp.async.ca.shared.global [%0], [%1], 16;\n" :: "r"(dst), "l"(src));
}
#define CP_COMMIT asm volatile("cp.async.commit_group;\n")

#define SA 40
#define ARRE (64 * SA)

__device__ __forceinline__ void grid_bar() {
    __syncthreads();
    if (threadIdx.x == 0) {
        __threadfence();
        const unsigned gen = g_gen;
        if (atomicAdd(&g_cnt, 1u) == CHB - 1) {
            g_cnt = 0;
            __threadfence();
            g_gen = gen + 1;
        } else {
            while (g_gen == gen) { __nanosleep(64); }
        }
        __threadfence();
    }
    __syncthreads();
}

// shared fragment-load + mma over one BK=32 stage
__device__ __forceinline__ void stage_mma(
    const bf* base, int wm, int wn, int lr, int lc, float acc[2][2][4])
{
    const bf* Ah = base;
    const bf* Al = base + ARRE;
    const bf* Bh = base + 2 * ARRE;
    const bf* Bl = base + 3 * ARRE;
    #pragma unroll
    for (int s = 0; s < 2; ++s) {
        const int kb = s * 16;
        unsigned a_h[2][4], a_l[2][4], b_h[2][2], b_l[2][2];
        #pragma unroll
        for (int mt = 0; mt < 2; ++mt) {
            const bf* p = Ah + (wm + mt * 16 + lr) * SA + kb + lc * 2;
            const bf* q = Al + (wm + mt * 16 + lr) * SA + kb + lc * 2;
            a_h[mt][0] = ld32bf(p);
            a_h[mt][1] = ld32bf(p + 8 * SA);
            a_h[mt][2] = ld32bf(p + 8);
            a_h[mt][3] = ld32bf(p + 8 * SA + 8);
            a_l[mt][0] = ld32bf(q);
            a_l[mt][1] = ld32bf(q + 8 * SA);
            a_l[mt][2] = ld32bf(q + 8);
            a_l[mt][3] = ld32bf(q + 8 * SA + 8);
        }
        #pragma unroll
        for (int nt = 0; nt < 2; ++nt) {
            const bf* p = Bh + (wn + nt * 8 + lr) * SA + kb + lc * 2;
            const bf* q = Bl + (wn + nt * 8 + lr) * SA + kb + lc * 2;
            b_h[nt][0] = ld32bf(p);
            b_h[nt][1] = ld32bf(p + 8);
            b_l[nt][0] = ld32bf(q);
            b_l[nt][1] = ld32bf(q + 8);
        }
        #pragma unroll
        for (int mt = 0; mt < 2; ++mt)
            #pragma unroll
            for (int nt = 0; nt < 2; ++nt) {
                MMA16816(acc[mt][nt], a_h[mt], b_h[nt]);
                MMA16816(acc[mt][nt], a_h[mt], b_l[nt]);
                MMA16816(acc[mt][nt], a_l[mt], b_h[nt]);
            }
    }
}

// 64x64 tile GEMM over K=512, A/B bf16 pairs (row-major, ld=HIDP), 2-stage
__device__ __forceinline__ void tile_gemm512(
    const bf* __restrict__ Agh, const bf* __restrict__ Agl,
    const bf* __restrict__ Bgh, const bf* __restrict__ Bgl,
    int m0, int n0, bf* sm, float acc[2][2][4])
{
    const unsigned smb = (unsigned)__cvta_generic_to_shared(sm);
    constexpr unsigned ARRB = ARRE * 2;
    constexpr unsigned STAGEB = 4 * ARRB;

    const int tid  = threadIdx.x;
    const int wid  = tid >> 5;
    const int lane = tid & 31;
    const int wm   = (wid >> 2) * 32;
    const int wn   = (wid & 3) * 16;
    const int lr   = lane >> 2;
    const int lc   = lane & 3;
    const int ar   = tid >> 2;
    const int ac   = (tid & 3) * 8;

    auto issue = [&](int k0, int st) {
        const size_t ao = (size_t)(m0 + ar) * HIDP + k0 + ac;
        const size_t bo = (size_t)(n0 + ar) * HIDP + k0 + ac;
        const unsigned d = smb + st * STAGEB + (unsigned)(ar * SA + ac) * 2;
        cp16(d,            Agh + ao);
        cp16(d + ARRB,     Agl + ao);
        cp16(d + 2 * ARRB, Bgh + bo);
        cp16(d + 3 * ARRB, Bgl + bo);
        CP_COMMIT;
    };

    issue(0, 0);
    #pragma unroll 1
    for (int i = 0; i < 16; ++i) {
        if (i + 1 < 16) {
            issue((i + 1) * 32, (i + 1) & 1);
            asm volatile("cp.async.wait_group 1;\n");
        } else {
            asm volatile("cp.async.wait_group 0;\n");
        }
        __syncthreads();
        stage_mma(sm + (i & 1) * 4 * ARRE, wm, wn, lr, lc, acc);
        __syncthreads();
    }
}

// ---------------------------------------------------------------------------
// Persistent chain kernel: pad/split -> 5 squarings (pair + transposed pair)
// -> hidden = h0aug @ (W^32)^T written fp32 to hidOut. ONE launch, 64 blocks,
// run ALONE on the device (no concurrent kernels -> barrier never straggles).
// ---------------------------------------------------------------------------
__global__ __launch_bounds__(256)
void chain_kernel(const float* __restrict__ W, const float* __restrict__ b,
                  const float* __restrict__ h0, float* __restrict__ hidOut)
{
    __shared__ __align__(16) bf sm[2 * 4 * ARRE];   // 40 KB

    const int tid  = threadIdx.x;
    const int wid  = tid >> 5;
    const int lane = tid & 31;
    const int wm   = (wid >> 2) * 32;
    const int wn   = (wid & 3) * 16;
    const int lr   = lane >> 2;
    const int lc   = lane & 3;
    const int bx   = blockIdx.x & 7;
    const int by   = blockIdx.x >> 3;
    const int m0   = by * 64;
    const int n0   = bx * 64;

    // ---- phase 0: pad + split W (and W^T) and h0aug
    for (int idx = blockIdx.x * 256 + tid; idx < HIDP * HIDP; idx += CHB * 256) {
        const int r = idx >> 9, c = idx & (HIDP - 1);
        float wv = 0.f;
        if (r < HID) {
            if (c < HID) wv = W[r * HID + c];
            else if (c == HID) wv = b[r];
        } else if (r == HID && c == HID) wv = 1.f;
        bf h, l;
        split_pair(wv, h, l);
        g_Wh[idx] = h;  g_Wl[idx] = l;
        g_WTh[c * HIDP + r] = h;  g_WTl[c * HIDP + r] = l;
        float hv = (c < HID) ? h0[r * HID + c] : (c == HID ? 1.f : 0.f);
        split_pair(hv, g_h0h[idx], g_h0l[idx]);
    }
    grid_bar();

    // ---- phases 1..5: squarings
    const bf *sh = g_Wh, *sl = g_Wl, *sth = g_WTh, *stl = g_WTl;
    bf* dh [5] = { g_M0h,  g_M1h,  g_M0h,  g_M1h,  g_M0h  };
    bf* dl [5] = { g_M0l,  g_M1l,  g_M0l,  g_M1l,  g_M0l  };
    bf* dth[5] = { g_M0Th, g_M1Th, g_M0Th, g_M1Th, g_M0Th };
    bf* dtl[5] = { g_M0Tl, g_M1Tl, g_M0Tl, g_M1Tl, g_M0Tl };

    for (int it = 0; it < 5; ++it) {
        float acc[2][2][4] = {};
        tile_gemm512(sh, sl, sth, stl, m0, n0, sm, acc);

        // stage pair into smem for transposed write; also write direct pair
        bf* th = sm;                 // [64][65]
        bf* tl = sm + 64 * 65;
        __syncthreads();             // smem free after k-loop
        #pragma unroll
        for (int mt = 0; mt < 2; ++mt)
            #pragma unroll
            for (int nt = 0; nt < 2; ++nt)
                #pragma unroll
                for (int rr = 0; rr < 2; ++rr) {
                    const int rl = wm + mt * 16 + lr + rr * 8;
                    #pragma unroll
                    for (int j = 0; j < 2; ++j) {
                        const int cl = wn + nt * 8 + lc * 2 + j;
                        bf h, l;
                        split_pair(acc[mt][nt][rr * 2 + j], h, l);
                        const size_t gi = (size_t)(m0 + rl) * HIDP + n0 + cl;
                        dh[it][gi] = h;
                        dl[it][gi] = l;
                        th[rl * 65 + cl] = h;
                        tl[rl * 65 + cl] = l;
                    }
                }
        if (it < 4) {
            __syncthreads();
            for (int e = tid; e < 64 * 64; e += 256) {
                const int r = e >> 6, c = e & 63;
                const size_t gi = (size_t)(n0 + r) * HIDP + m0 + c;
                dth[it][gi] = th[c * 65 + r];
                dtl[it][gi] = tl[c * 65 + r];
            }
        }
        grid_bar();
        sh = dh[it]; sl = dl[it]; sth = dth[it]; stl = dtl[it];
    }

    // ---- phase 6: hidden = h0aug @ (W^32)^T
    {
        float acc[2][2][4] = {};
        tile_gemm512(g_h0h, g_h0l, g_M0h, g_M0l, m0, n0, sm, acc);
        #pragma unroll
        for (int mt = 0; mt < 2; ++mt)
            #pragma unroll
            for (int nt = 0; nt < 2; ++nt)
                #pragma unroll
                for (int rr = 0; rr < 2; ++rr) {
                    const int r = m0 + wm + mt * 16 + lr + rr * 8;
                    #pragma unroll
                    for (int j = 0; j < 2; ++j) {
                        const int c = n0 + wn + nt * 8 + lc * 2 + j;
                        if (c < HID)
                            hidOut[(size_t)r * HID + c] = acc[mt][nt][rr * 2 + j];
                    }
                }
    }
}

// ---------------------------------------------------------------------------
// l2_gemm: pair A (cp.async), fp32 B (register-prefetch + split in staging),
// split-K -> fp32 partials. B is (N,K)=(500,9504) row-major fp32.
// ---------------------------------------------------------------------------
__global__ __launch_bounds__(256)
void l2_gemm(const bf* __restrict__ Agh, const bf* __restrict__ Agl,
             const float* __restrict__ Bf,
             float* __restrict__ C)
{
    __shared__ __align__(16) bf sm[2 * 4 * ARRE];
    const unsigned smb = (unsigned)__cvta_generic_to_shared(sm);
    constexpr unsigned ARRB = ARRE * 2;
    constexpr unsigned STAGEB = 4 * ARRB;

    const int tid  = threadIdx.x;
    const int wid  = tid >> 5;
    const int lane = tid & 31;
    const int wm   = (wid >> 2) * 32;
    const int wn   = (wid & 3) * 16;
    const int lr   = lane >> 2;
    const int lc   = lane & 3;
    const int m0   = blockIdx.y * 64;
    const int n0   = blockIdx.x * 64;
    const int kbeg = blockIdx.z * L2LEN;
    C += (size_t)blockIdx.z * (size_t)NB * (size_t)HID;

    float acc[2][2][4] = {};
    const int ar = tid >> 2;
    const int ac = (tid & 3) * 8;
    const bool bvalid = (n0 + ar) < HID;
    const float* brow = Bf + (size_t)(n0 + ar) * YK;

    float4 rB0, rB1;

    auto issueA = [&](int k0, int st) {
        const size_t ao = (size_t)(m0 + ar) * YK + k0 + ac;
        const unsigned d = smb + st * STAGEB + (unsigned)(ar * SA + ac) * 2;
        cp16(d,        Agh + ao);
        cp16(d + ARRB, Agl + ao);
        CP_COMMIT;
    };
    auto loadB = [&](int k0) {
        if (bvalid) {
            rB0 = *reinterpret_cast<const float4*>(brow + k0 + ac);
            rB1 = *reinterpret_cast<const float4*>(brow + k0 + ac + 4);
        } else {
            rB0 = make_float4(0.f, 0.f, 0.f, 0.f);
            rB1 = make_float4(0.f, 0.f, 0.f, 0.f);
        }
    };
    auto storeB = [&](int st) {
        bf* Bh = sm + st * 4 * ARRE + 2 * ARRE + ar * SA + ac;
        bf* Bl = Bh + ARRE;
        const float v[8] = { rB0.x, rB0.y, rB0.z, rB0.w, rB1.x, rB1.y, rB1.z, rB1.w };
        uint4 vh, vl;
        bf* hv = reinterpret_cast<bf*>(&vh);
        bf* lv = reinterpret_cast<bf*>(&vl);
        #pragma unroll
        for (int e = 0; e < 8; ++e) split_pair(v[e], hv[e], lv[e]);
        *reinterpret_cast<uint4*>(Bh) = vh;
        *reinterpret_cast<uint4*>(Bl) = vl;
    };

    constexpr int nit = L2LEN / 32;
    issueA(kbeg, 0);
    loadB(kbeg);
    for (int i = 0; i < nit; ++i) {
        if (i + 1 < nit) issueA(kbeg + (i + 1) * 32, (i + 1) & 1);
        storeB(i & 1);
        if (i + 1 < nit) asm volatile("cp.async.wait_group 1;\n");
        else             asm volatile("cp.async.wait_group 0;\n");
        __syncthreads();
        if (i + 1 < nit) loadB(kbeg + (i + 1) * 32);
        stage_mma(sm + (i & 1) * 4 * ARRE, wm, wn, lr, lc, acc);
        __syncthreads();
    }

    #pragma unroll
    for (int mt = 0; mt < 2; ++mt)
        #pragma unroll
        for (int nt = 0; nt < 2; ++nt)
            #pragma unroll
            for (int rr = 0; rr < 2; ++rr) {
                const int r = m0 + wm + mt * 16 + lr + rr * 8;
                #pragma unroll
                for (int j = 0; j < 2; ++j) {
                    const int c = n0 + wn + nt * 8 + lc * 2 + j;
                    if (c < HID) C[(size_t)r * HID + c] = acc[mt][nt][rr * 2 + j];
                }
            }
}

// ---------------------------------------------------------------------------
// fc GEMM with register-prefetch double buffering (fp32 dual weights).
__global__ __launch_bounds__(256)
void fc_gemm(const bf* __restrict__ Agh, const bf* __restrict__ Agl,
             const float* __restrict__ Bf, const float* __restrict__ bias,
             const float* __restrict__ Bf2, const float* __restrict__ bias2,
             float* __restrict__ C)
{
    constexpr int BK = 16, FSA = 24, FARRE = 64 * FSA;
    __shared__ __align__(16) bf smf[4 * FARRE];
    bf* Ah = smf;
    bf* Al = smf + FARRE;
    bf* Bh = smf + 2 * FARRE;
    bf* Bl = smf + 3 * FARRE;

    const int tid  = threadIdx.x;
    const int wid  = tid >> 5;
    const int lane = tid & 31;
    const int wm   = (wid >> 2) * 32;
    const int wn   = (wid & 3) * 16;
    const int lr   = lane >> 2;
    const int lc   = lane & 3;
    const int m0   = blockIdx.y * 64;
    const int n0   = blockIdx.x * 64;
    const int N = HF, K = FEAT;

    if (blockIdx.y >= (gridDim.y >> 1)) { Bf = Bf2; bias = bias2; }

    float acc[2][2][4] = {};
    const int ar = tid >> 2;
    const int ac = (tid & 3) * 4;

    uint2 rAh, rAl;
    float4 rB;

    auto loadT = [&](int k0) {
        const size_t aoff = (size_t)(m0 + ar) * K + k0 + ac;
        rAh = *reinterpret_cast<const uint2*>(Agh + aoff);
        rAl = *reinterpret_cast<const uint2*>(Agl + aoff);
        if (n0 + ar < N)
            rB = *reinterpret_cast<const float4*>(&Bf[(size_t)(n0 + ar) * K + k0 + ac]);
        else
            rB = make_float4(0.f, 0.f, 0.f, 0.f);
    };
    auto storeT = [&]() {
        *reinterpret_cast<uint2*>(Ah + ar * FSA + ac) = rAh;
        *reinterpret_cast<uint2*>(Al + ar * FSA + ac) = rAl;
        split_pair(rB.x, Bh[ar * FSA + ac + 0], Bl[ar * FSA + ac + 0]);
        split_pair(rB.y, Bh[ar * FSA + ac + 1], Bl[ar * FSA + ac + 1]);
        split_pair(rB.z, Bh[ar * FSA + ac + 2], Bl[ar * FSA + ac + 2]);
        split_pair(rB.w, Bh[ar * FSA + ac + 3], Bl[ar * FSA + ac + 3]);
    };

    loadT(0);
    for (int k0 = 0; k0 < K; k0 += BK) {
        storeT();
        __syncthreads();
        if (k0 + BK < K) loadT(k0 + BK);

        unsigned a_h[2][4], a_l[2][4], b_h[2][2], b_l[2][2];
        #pragma unroll
        for (int mt = 0; mt < 2; ++mt) {
            const bf* p = Ah + (wm + mt * 16 + lr) * FSA + lc * 2;
            const bf* q = Al + (wm + mt * 16 + lr) * FSA + lc * 2;
            a_h[mt][0] = ld32bf(p);
            a_h[mt][1] = ld32bf(p + 8 * FSA);
            a_h[mt][2] = ld32bf(p + 8);
            a_h[mt][3] = ld32bf(p + 8 * FSA + 8);
            a_l[mt][0] = ld32bf(q);
            a_l[mt][1] = ld32bf(q + 8 * FSA);
            a_l[mt][2] = ld32bf(q + 8);
            a_l[mt][3] = ld32bf(q + 8 * FSA + 8);
        }
        #pragma unroll
        for (int nt = 0; nt < 2; ++nt) {
            const bf* p = Bh + (wn + nt * 8 + lr) * FSA + lc * 2;
            const bf* q = Bl + (wn + nt * 8 + lr) * FSA + lc * 2;
            b_h[nt][0] = ld32bf(p);
            b_h[nt][1] = ld32bf(p + 8);
            b_l[nt][0] = ld32bf(q);
            b_l[nt][1] = ld32bf(q + 8);
        }
        #pragma unroll
        for (int mt = 0; mt < 2; ++mt)
            #pragma unroll
            for (int nt = 0; nt < 2; ++nt) {
                MMA16816(acc[mt][nt], a_h[mt], b_h[nt]);
                MMA16816(acc[mt][nt], a_h[mt], b_l[nt]);
                MMA16816(acc[mt][nt], a_l[mt], b_h[nt]);
            }
        __syncthreads();
    }

    #pragma unroll
    for (int mt = 0; mt < 2; ++mt)
        #pragma unroll
        for (int nt = 0; nt < 2; ++nt)
            #pragma unroll
            for (int rr = 0; rr < 2; ++rr) {
                const int r = m0 + wm + mt * 16 + lr + rr * 8;
                #pragma unroll
                for (int j = 0; j < 2; ++j) {
                    const int c = n0 + wn + nt * 8 + lc * 2 + j;
                    if (c < N)
                        C[(size_t)r * HF + c] = fmaxf(acc[mt][nt][rr * 2 + j] + bias[c], 0.f);
                }
            }
}

// ---------------------------------------------------------------------------
// hand branch: conv1d(k=2,2->16) + relu + pool2 -> feat pair
__global__ void hand_feat_kernel(const float* __restrict__ hd,
                                 const float* __restrict__ lcw, const float* __restrict__ lcb,
                                 const float* __restrict__ rcw, const float* __restrict__ rcb,
                                 int tOff)
{
    const int s    = blockIdx.x;
    const int n    = s & (NB - 1);
    const int hand = s >> 9;
    const float* x  = hd + tOff + n * 84 + hand * 42;
    const float* cw = hand ? rcw : lcw;
    const float* cb = hand ? rcb : lcb;

    __shared__ float xs[42];
    __shared__ float z[16 * 20];
    const int tid = threadIdx.x;
    if (tid < 42) xs[tid] = x[tid];
    __syncthreads();

    for (int idx = tid; idx < 320; idx += 128) {
        int o = idx / 20, j = idx % 20;
        float v = cb[o]
                + cw[o * 4 + 0] * xs[2 * j]
                + cw[o * 4 + 1] * xs[2 * j + 2]
                + cw[o * 4 + 2] * xs[2 * j + 1]
                + cw[o * 4 + 3] * xs[2 * j + 3];
        z[o * 20 + j] = fmaxf(v, 0.f);
    }
    __syncthreads();

    for (int idx = tid; idx < FEAT; idx += 128) {
        int o = idx / 19, j = idx % 19;
        float v = fmaxf(z[o * 20 + j], z[o * 20 + j + 1]);
        split_pair(v, g_feath[(size_t)s * FEAT + idx], g_featl[(size_t)s * FEAT + idx]);
    }
}

// conv2(k=2,2->32) + relu + pool3 -> y pair; 2 blocks per sample (16 ch each)
__global__ __launch_bounds__(256)
void conv2pool_kernel(const float* __restrict__ w2, const float* __restrict__ b2)
{
    __shared__ float slo[HF], sro[HF], sw[128], sb[32];
    const int n    = blockIdx.x;
    const int half = blockIdx.y;
    const int tid  = threadIdx.x;
    const int wid  = tid >> 5;
    const int lane = tid & 31;
    for (int i = tid; i < HF; i += 256) {
        slo[i] = g_both[(size_t)n * HF + i];
        sro[i] = g_both[(size_t)(NB + n) * HF + i];
    }
    if (tid < 128) sw[tid] = w2[tid];
    if (tid < 32)  sb[tid] = b2[tid];
    __syncthreads();

    #pragma unroll
    for (int oo = 0; oo < 2; ++oo) {
        const int o = half * 16 + oo * 8 + wid;
        const float w00 = sw[o * 4 + 0], w01 = sw[o * 4 + 1];
        const float w10 = sw[o * 4 + 2], w11 = sw[o * 4 + 3];
        const float bb = sb[o];
        const size_t obase = (size_t)n * YK + o * 297;
        for (int jj = lane; jj < 297; jj += 32) {
            float l0 = slo[jj], l1 = slo[jj + 1], l2v = slo[jj + 2], l3 = slo[jj + 3];
            float r0 = sro[jj], r1 = sro[jj + 1], r2v = sro[jj + 2], r3 = sro[jj + 3];
            float z0 = bb + w00 * l0  + w01 * l1  + w10 * r0  + w11 * r1;
            float z1 = bb + w00 * l1  + w01 * l2v + w10 * r1  + w11 * r2v;
            float z2 = bb + w00 * l2v + w01 * l3  + w10 * r2v + w11 * r3;
            float v = fmaxf(fmaxf(z0, z1), fmaxf(z2, 0.f));
            split_pair(v, g_yh[obase + jj], g_yl[obase + jj]);
        }
    }
}

// final: i2h = sum(part)+l2b; out = relu((i2h + hid)@ow^T + ob)
__global__ __launch_bounds__(512)
void out_kernel(const float* __restrict__ part,
                const float* __restrict__ hid,
                const float* __restrict__ l2b,
                const float* __restrict__ ow,
                const float* __restrict__ ob,
                float* __restrict__ out)
{
    __shared__ float val[HID];
    const int n   = blockIdx.x;
    const int tid = threadIdx.x;

    if (tid < HID) {
        const size_t o = (size_t)n * HID + tid;
        float is = l2b[tid];
        #pragma unroll
        for (int s = 0; s < L2S; ++s) is += part[(size_t)s * NB * HID + o];
        val[tid] = hid[o] + is;
    }
    __syncthreads();

    if (tid < OUT * 32) {
        const int m    = tid >> 5;
        const int lane = tid & 31;
        const float* w = ow + (size_t)m * HID;
        float s = 0.f;
        for (int k = lane; k < HID; k += 32) s += val[k] * w[k];
        #pragma unroll
        for (int o = 16; o; o >>= 1) s += __shfl_down_sync(0xffffffffu, s, o);
        if (lane == 0) out[n * OUT + m] = fmaxf(s + ob[m], 0.f);
    }
}

// ---------------------------------------------------------------------------
extern "C" void kernel_launch(void* const* d_in, const int* in_sizes, int n_in,
                              void* d_out, int out_size)
{
    const float* hand_data = (const float*)d_in[0];
    const float* hidden    = (const float*)d_in[1];
    const float* l_conv_w  = (const float*)d_in[2];
    const float* l_conv_b  = (const float*)d_in[3];
    const float* l_fc_w    = (const float*)d_in[4];
    const float* l_fc_b    = (const float*)d_in[5];
    const float* r_conv_w  = (const float*)d_in[6];
    const float* r_conv_b  = (const float*)d_in[7];
    const float* r_fc_w    = (const float*)d_in[8];
    const float* r_fc_b    = (const float*)d_in[9];
    const float* conv2_w   = (const float*)d_in[10];
    const float* conv2_b   = (const float*)d_in[11];
    const float* l2_w      = (const float*)d_in[12];
    const float* l2_b      = (const float*)d_in[13];
    const float* h2h_w     = (const float*)d_in[14];
    const float* h2h_b     = (const float*)d_in[15];
    const float* out_w     = (const float*)d_in[16];
    const float* out_b     = (const float*)d_in[17];

    const int T    = in_sizes[0] / (NB * 84);
    const int tOff = (T - 1) * NB * 84;

    bf *feath, *featl, *yh, *yl;
    float *both, *part, *hid;
    cudaGetSymbolAddress((void**)&feath, g_feath);
    cudaGetSymbolAddress((void**)&featl, g_featl);
    cudaGetSymbolAddress((void**)&both,  g_both);
    cudaGetSymbolAddress((void**)&yh,    g_yh);
    cudaGetSymbolAddress((void**)&yl,    g_yl);
    cudaGetSymbolAddress((void**)&part,  g_part);
    cudaGetSymbolAddress((void**)&hid,   g_hid);

    float* hidOut = (out_size >= NB * OUT + NB * HID) ? ((float*)d_out) + NB * OUT : hid;

    // single stream, strictly sequential — the persistent chain kernel runs
    // alone on the device so its grid barrier never waits on contention.
    chain_kernel<<<CHB, 256>>>(h2h_w, h2h_b, hidden, hidOut);
    hand_feat_kernel<<<1024, 128>>>(hand_data, l_conv_w, l_conv_b, r_conv_w, r_conv_b, tOff);
    fc_gemm<<<dim3(5, 16), 256>>>(feath, featl, l_fc_w, l_fc_b, r_fc_w, r_fc_b, both);
    conv2pool_kernel<<<dim3(NB, 2), 256>>>(conv2_w, conv2_b);
    l2_gemm<<<dim3(8, 8, L2S), 256>>>(yh, yl, l2_w, part);
    out_kernel<<<NB, 512>>>(part, hidOut, l2_b, out_w, out_b, (float*)d_out);
}

// round 11
// speedup vs baseline: 1.4359x; 1.4359x over previous
#include <cuda_runtime.h>
#include <cuda_bf16.h>

// ---------------------------------------------------------------------------
// ASLRNN3 sm_100a.  R9 structure (best: 160.1us) + ldmatrix fragment loads
// (replaces 48 scalar LDS.32 per BK=32 iter with 12 ldmatrix.x4 — same bits,
// 4x fewer LSU ops). Persistent-chain experiments (R6/R10) are dead: the
// split-K chain on a side stream overlapped with the front-end wins.
//  * only last frame feeds outs[-1]
//  * hidden recurrence: affine, i2h-independent -> homogeneous 501x501 power
//    via 5 squarings (512-pad), split-K=8 + reduce, on a side stream.
//  * all GEMMs: bf16 hi/lo split 3-MMA, fp32 accum, cp.async 2-stage.
// ---------------------------------------------------------------------------

#define NB 512
#define FEAT 304
#define HF 300
#define YK 9504
#define HID 500
#define HIDP 512
#define OUT 10
#define L2S 11         // l2 split-K  (9504 = 11*864, 864 = 27*32)
#define L2LEN 864
#define CHS 8          // chain split-K (512 = 8*64)
#define CHLEN 64

typedef __nv_bfloat16 bf;

// ---- scratch ----
__device__ bf g_feath[1024 * FEAT];
__device__ bf g_featl[1024 * FEAT];
__device__ float g_both[1024 * HF];
__device__ bf g_yh[NB * YK];
__device__ bf g_yl[NB * YK];
__device__ float g_part[L2S * NB * HID];
__device__ float g_cpart[CHS * HIDP * HIDP];
__device__ float g_hpart[CHS * NB * HID];
__device__ bf g_Wh [HIDP * HIDP];
__device__ bf g_Wl [HIDP * HIDP];
__device__ bf g_WTh[HIDP * HIDP];
__device__ bf g_WTl[HIDP * HIDP];
__device__ bf g_M0h[HIDP * HIDP];
__device__ bf g_M0l[HIDP * HIDP];
__device__ bf g_M0Th[HIDP * HIDP];
__device__ bf g_M0Tl[HIDP * HIDP];
__device__ bf g_M1h[HIDP * HIDP];
__device__ bf g_M1l[HIDP * HIDP];
__device__ bf g_M1Th[HIDP * HIDP];
__device__ bf g_M1Tl[HIDP * HIDP];
__device__ bf g_h0h[NB * HIDP];
__device__ bf g_h0l[NB * HIDP];
__device__ float g_hid[NB * HID];

#define MMA16816(c, a, b) asm volatile( \
    "mma.sync.aligned.m16n8k16.row.col.f32.bf16.bf16.f32 " \
    "{%0,%1,%2,%3},{%4,%5,%6,%7},{%8,%9},{%0,%1,%2,%3};\n" \
    : "+f"((c)[0]), "+f"((c)[1]), "+f"((c)[2]), "+f"((c)[3]) \
    : "r"((a)[0]), "r"((a)[1]), "r"((a)[2]), "r"((a)[3]), \
      "r"((b)[0]), "r"((b)[1]))

__device__ __forceinline__ void split_pair(float x, bf& h, bf& l) {
    h = __float2bfloat16(x);
    l = __float2bfloat16(x - __bfloat162float(h));
}
__device__ __forceinline__ void cp16(unsigned dst, const void* src) {
    asm volatile("cp.async.ca.shared.global [%0], [%1], 16;\n" :: "r"(dst), "l"(src));
}
#define CP_COMMIT asm volatile("cp.async.commit_group;\n")

#define SA 40
#define ARRE (64 * SA)

__device__ __forceinline__ void ldsm4(unsigned addr, unsigned* r) {
    asm volatile("ldmatrix.sync.aligned.m8n8.x4.shared.b16 {%0,%1,%2,%3}, [%4];"
        : "=r"(r[0]), "=r"(r[1]), "=r"(r[2]), "=r"(r[3]) : "r"(addr));
}

// One (or two) 16-k-step(s) of the hi/lo 3-MMA scheme using ldmatrix loads.
// base = smem byte address of this stage's Ah array; layout Ah|Al|Bh|Bl each
// ARR elements (row stride ST bf16). Fragment mapping identical to the
// previous scalar loads (verified against mma.m16n8k16 operand layout).
template<int ST, int ARR, int NS>
__device__ __forceinline__ void stage_mma_u(unsigned base, int wm, int wn,
                                            int lane, float acc[2][2][4])
{
    constexpr unsigned AB = ARR * 2;          // array bytes
    const int arow = lane & 15;
    const int acol = (lane >> 4) * 8;
    const int bg   = lane >> 3;
    const int brow = (bg >> 1) * 8 + (lane & 7);
    const int bcol = (bg & 1) * 8;
    #pragma unroll
    for (int s = 0; s < NS; ++s) {
        const int kb = s * 16;
        unsigned a_h[2][4], a_l[2][4], b_h[4], b_l[4];
        #pragma unroll
        for (int mt = 0; mt < 2; ++mt) {
            const unsigned ao = (unsigned)(((wm + mt * 16 + arow) * ST + kb + acol) * 2);
            ldsm4(base + ao,      a_h[mt]);
            ldsm4(base + AB + ao, a_l[mt]);
        }
        const unsigned bo = (unsigned)(((wn + brow) * ST + kb + bcol) * 2);
        ldsm4(base + 2 * AB + bo, b_h);
        ldsm4(base + 3 * AB + bo, b_l);
        #pragma unroll
        for (int mt = 0; mt < 2; ++mt)
            #pragma unroll
            for (int nt = 0; nt < 2; ++nt) {
                MMA16816(acc[mt][nt], a_h[mt], b_h + nt * 2);
                MMA16816(acc[mt][nt], a_h[mt], b_l + nt * 2);
                MMA16816(acc[mt][nt], a_l[mt], b_h + nt * 2);
            }
    }
}

// ---------------------------------------------------------------------------
// pp_gemm: pair A, pair B, split-K -> fp32 partials (chain + hidden GEMMs)
// ---------------------------------------------------------------------------
__global__ __launch_bounds__(256)
void pp_gemm(int M, int N, int K,
             const bf* __restrict__ Agh, const bf* __restrict__ Agl, int lda,
             const bf* __restrict__ Bgh, const bf* __restrict__ Bgl, int ldb,
             float* __restrict__ C, int ldc, int splitLen)
{
    __shared__ __align__(16) bf sm[2 * 4 * ARRE];
    const unsigned smb = (unsigned)__cvta_generic_to_shared(sm);
    constexpr unsigned ARRB = ARRE * 2;
    constexpr unsigned STAGEB = 4 * ARRB;

    const int tid  = threadIdx.x;
    const int wid  = tid >> 5;
    const int lane = tid & 31;
    const int wm   = (wid >> 2) * 32;
    const int wn   = (wid & 3) * 16;
    const int lr   = lane >> 2;
    const int lc   = lane & 3;
    const int m0   = blockIdx.y * 64;
    const int n0   = blockIdx.x * 64;

    const int kbeg = blockIdx.z * splitLen;
    const int kend = min(K, kbeg + splitLen);
    C += (size_t)blockIdx.z * (size_t)M * (size_t)ldc;

    float acc[2][2][4] = {};
    const int ar = tid >> 2;
    const int ac = (tid & 3) * 8;

    auto issue = [&](int k0, int st) {
        const size_t ao = (size_t)(m0 + ar) * lda + k0 + ac;
        const size_t bo = (size_t)(n0 + ar) * ldb + k0 + ac;
        const unsigned d = smb + st * STAGEB + (unsigned)(ar * SA + ac) * 2;
        cp16(d,            Agh + ao);
        cp16(d + ARRB,     Agl + ao);
        cp16(d + 2 * ARRB, Bgh + bo);
        cp16(d + 3 * ARRB, Bgl + bo);
        CP_COMMIT;
    };

    const int nit = (kend - kbeg) / 32;
    issue(kbeg, 0);
    for (int i = 0; i < nit; ++i) {
        if (i + 1 < nit) {
            issue(kbeg + (i + 1) * 32, (i + 1) & 1);
            asm volatile("cp.async.wait_group 1;\n");
        } else {
            asm volatile("cp.async.wait_group 0;\n");
        }
        __syncthreads();
        stage_mma_u<SA, ARRE, 2>(smb + (i & 1) * STAGEB, wm, wn, lane, acc);
        __syncthreads();
    }

    #pragma unroll
    for (int mt = 0; mt < 2; ++mt)
        #pragma unroll
        for (int nt = 0; nt < 2; ++nt)
            #pragma unroll
            for (int rr = 0; rr < 2; ++rr) {
                const int r = m0 + wm + mt * 16 + lr + rr * 8;
                #pragma unroll
                for (int j = 0; j < 2; ++j) {
                    const int c = n0 + wn + nt * 8 + lc * 2 + j;
                    if (c < N) C[(size_t)r * ldc + c] = acc[mt][nt][rr * 2 + j];
                }
            }
}

// ---------------------------------------------------------------------------
// reduce CHS fp32 partials -> bf16 pair (+ optional transposed pair), 512x512
template<bool WRITET>
__global__ __launch_bounds__(256)
void reduce_split(const float* __restrict__ part,
                  bf* __restrict__ Dh, bf* __restrict__ Dl,
                  bf* __restrict__ DTh, bf* __restrict__ DTl)
{
    __shared__ bf th[32][33], tl[32][33];
    const int bx = blockIdx.x * 32, by = blockIdx.y * 32;
    const int x = threadIdx.x & 31;
    const int y0 = threadIdx.x >> 5;
    #pragma unroll
    for (int dy = 0; dy < 32; dy += 8) {
        const int r = by + y0 + dy, c = bx + x;
        const size_t idx = (size_t)r * HIDP + c;
        float v = part[idx];
        #pragma unroll
        for (int s = 1; s < CHS; ++s) v += part[(size_t)s * HIDP * HIDP + idx];
        bf h, l;
        split_pair(v, h, l);
        Dh[idx] = h; Dl[idx] = l;
        th[y0 + dy][x] = h; tl[y0 + dy][x] = l;
    }
    if (WRITET) {
        __syncthreads();
        #pragma unroll
        for (int dy = 0; dy < 32; dy += 8) {
            const int r = bx + y0 + dy, c = by + x;
            const size_t idx = (size_t)r * HIDP + c;
            DTh[idx] = th[x][y0 + dy];
            DTl[idx] = tl[x][y0 + dy];
        }
    }
}

// ---------------------------------------------------------------------------
// l2_gemm: pair A (cp.async), fp32 B (register-prefetch + split in staging),
// split-K -> fp32 partials. B is (N,K)=(500,9504) row-major fp32.
// ---------------------------------------------------------------------------
__global__ __launch_bounds__(256)
void l2_gemm(const bf* __restrict__ Agh, const bf* __restrict__ Agl,
             const float* __restrict__ Bf,
             float* __restrict__ C)
{
    __shared__ __align__(16) bf sm[2 * 4 * ARRE];
    const unsigned smb = (unsigned)__cvta_generic_to_shared(sm);
    constexpr unsigned ARRB = ARRE * 2;
    constexpr unsigned STAGEB = 4 * ARRB;

    const int tid  = threadIdx.x;
    const int wid  = tid >> 5;
    const int lane = tid & 31;
    const int wm   = (wid >> 2) * 32;
    const int wn   = (wid & 3) * 16;
    const int lr   = lane >> 2;
    const int lc   = lane & 3;
    const int m0   = blockIdx.y * 64;
    const int n0   = blockIdx.x * 64;
    const int kbeg = blockIdx.z * L2LEN;
    C += (size_t)blockIdx.z * (size_t)NB * (size_t)HID;

    float acc[2][2][4] = {};
    const int ar = tid >> 2;
    const int ac = (tid & 3) * 8;
    const bool bvalid = (n0 + ar) < HID;
    const float* brow = Bf + (size_t)(n0 + ar) * YK;

    float4 rB0, rB1;

    auto issueA = [&](int k0, int st) {
        const size_t ao = (size_t)(m0 + ar) * YK + k0 + ac;
        const unsigned d = smb + st * STAGEB + (unsigned)(ar * SA + ac) * 2;
        cp16(d,        Agh + ao);
        cp16(d + ARRB, Agl + ao);
        CP_COMMIT;
    };
    auto loadB = [&](int k0) {
        if (bvalid) {
            rB0 = *reinterpret_cast<const float4*>(brow + k0 + ac);
            rB1 = *reinterpret_cast<const float4*>(brow + k0 + ac + 4);
        } else {
            rB0 = make_float4(0.f, 0.f, 0.f, 0.f);
            rB1 = make_float4(0.f, 0.f, 0.f, 0.f);
        }
    };
    auto storeB = [&](int st) {
        bf* Bh = sm + st * 4 * ARRE + 2 * ARRE + ar * SA + ac;
        bf* Bl = Bh + ARRE;
        const float v[8] = { rB0.x, rB0.y, rB0.z, rB0.w, rB1.x, rB1.y, rB1.z, rB1.w };
        uint4 vh, vl;
        bf* hv = reinterpret_cast<bf*>(&vh);
        bf* lv = reinterpret_cast<bf*>(&vl);
        #pragma unroll
        for (int e = 0; e < 8; ++e) split_pair(v[e], hv[e], lv[e]);
        *reinterpret_cast<uint4*>(Bh) = vh;
        *reinterpret_cast<uint4*>(Bl) = vl;
    };

    constexpr int nit = L2LEN / 32;
    issueA(kbeg, 0);
    loadB(kbeg);
    for (int i = 0; i < nit; ++i) {
        if (i + 1 < nit) issueA(kbeg + (i + 1) * 32, (i + 1) & 1);
        storeB(i & 1);
        if (i + 1 < nit) asm volatile("cp.async.wait_group 1;\n");
        else             asm volatile("cp.async.wait_group 0;\n");
        __syncthreads();
        if (i + 1 < nit) loadB(kbeg + (i + 1) * 32);
        stage_mma_u<SA, ARRE, 2>(smb + (i & 1) * STAGEB, wm, wn, lane, acc);
        __syncthreads();
    }

    #pragma unroll
    for (int mt = 0; mt < 2; ++mt)
        #pragma unroll
        for (int nt = 0; nt < 2; ++nt)
            #pragma unroll
            for (int rr = 0; rr < 2; ++rr) {
                const int r = m0 + wm + mt * 16 + lr + rr * 8;
                #pragma unroll
                for (int j = 0; j < 2; ++j) {
                    const int c = n0 + wn + nt * 8 + lc * 2 + j;
                    if (c < HID) C[(size_t)r * HID + c] = acc[mt][nt][rr * 2 + j];
                }
            }
}

// ---------------------------------------------------------------------------
// fc GEMM with register-prefetch double buffering (fp32 dual weights).
#define FSA 24
#define FARRE (64 * FSA)
__global__ __launch_bounds__(256)
void fc_gemm(const bf* __restrict__ Agh, const bf* __restrict__ Agl,
             const float* __restrict__ Bf, const float* __restrict__ bias,
             const float* __restrict__ Bf2, const float* __restrict__ bias2,
             float* __restrict__ C)
{
    constexpr int BK = 16;
    __shared__ __align__(16) bf smf[4 * FARRE];
    const unsigned smbf = (unsigned)__cvta_generic_to_shared(smf);
    bf* Ah = smf;
    bf* Al = smf + FARRE;
    bf* Bh = smf + 2 * FARRE;
    bf* Bl = smf + 3 * FARRE;

    const int tid  = threadIdx.x;
    const int wid  = tid >> 5;
    const int lane = tid & 31;
    const int wm   = (wid >> 2) * 32;
    const int wn   = (wid & 3) * 16;
    const int lr   = lane >> 2;
    const int lc   = lane & 3;
    const int m0   = blockIdx.y * 64;
    const int n0   = blockIdx.x * 64;
    const int N = HF, K = FEAT;

    if (blockIdx.y >= (gridDim.y >> 1)) { Bf = Bf2; bias = bias2; }

    float acc[2][2][4] = {};
    const int ar = tid >> 2;
    const int ac = (tid & 3) * 4;

    uint2 rAh, rAl;
    float4 rB;

    auto loadT = [&](int k0) {
        const size_t aoff = (size_t)(m0 + ar) * K + k0 + ac;
        rAh = *reinterpret_cast<const uint2*>(Agh + aoff);
        rAl = *reinterpret_cast<const uint2*>(Agl + aoff);
        if (n0 + ar < N)
            rB = *reinterpret_cast<const float4*>(&Bf[(size_t)(n0 + ar) * K + k0 + ac]);
        else
            rB = make_float4(0.f, 0.f, 0.f, 0.f);
    };
    auto storeT = [&]() {
        *reinterpret_cast<uint2*>(Ah + ar * FSA + ac) = rAh;
        *reinterpret_cast<uint2*>(Al + ar * FSA + ac) = rAl;
        split_pair(rB.x, Bh[ar * FSA + ac + 0], Bl[ar * FSA + ac + 0]);
        split_pair(rB.y, Bh[ar * FSA + ac + 1], Bl[ar * FSA + ac + 1]);
        split_pair(rB.z, Bh[ar * FSA + ac + 2], Bl[ar * FSA + ac + 2]);
        split_pair(rB.w, Bh[ar * FSA + ac + 3], Bl[ar * FSA + ac + 3]);
    };

    loadT(0);
    for (int k0 = 0; k0 < K; k0 += BK) {
        storeT();
        __syncthreads();
        if (k0 + BK < K) loadT(k0 + BK);
        stage_mma_u<FSA, FARRE, 1>(smbf, wm, wn, lane, acc);
        __syncthreads();
    }

    #pragma unroll
    for (int mt = 0; mt < 2; ++mt)
        #pragma unroll
        for (int nt = 0; nt < 2; ++nt)
            #pragma unroll
            for (int rr = 0; rr < 2; ++rr) {
                const int r = m0 + wm + mt * 16 + lr + rr * 8;
                #pragma unroll
                for (int j = 0; j < 2; ++j) {
                    const int c = n0 + wn + nt * 8 + lc * 2 + j;
                    if (c < N)
                        C[(size_t)r * HF + c] = fmaxf(acc[mt][nt][rr * 2 + j] + bias[c], 0.f);
                }
            }
}

// ---------------------------------------------------------------------------
__global__ void pad_kernel(const float* __restrict__ W,
                           const float* __restrict__ b,
                           const float* __restrict__ h0)
{
    int idx = blockIdx.x * blockDim.x + threadIdx.x;
    if (idx >= HIDP * HIDP) return;
    int r = idx >> 9, c = idx & (HIDP - 1);
    float wv = 0.f;
    if (r < HID) {
        if (c < HID) wv = W[r * HID + c];
        else if (c == HID) wv = b[r];
    } else if (r == HID && c == HID) wv = 1.f;
    bf h, l;
    split_pair(wv, h, l);
    g_Wh[idx] = h;  g_Wl[idx] = l;
    g_WTh[c * HIDP + r] = h;  g_WTl[c * HIDP + r] = l;
    float hv = (c < HID) ? h0[r * HID + c] : (c == HID ? 1.f : 0.f);
    split_pair(hv, g_h0h[idx], g_h0l[idx]);
}

// hand branch: conv1d(k=2,2->16) + relu + pool2 -> feat pair
__global__ void hand_feat_kernel(const float* __restrict__ hd,
                                 const float* __restrict__ lcw, const float* __restrict__ lcb,
                                 const float* __restrict__ rcw, const float* __restrict__ rcb,
                                 int tOff)
{
    const int s    = blockIdx.x;
    const int n    = s & (NB - 1);
    const int hand = s >> 9;
    const float* x  = hd + tOff + n * 84 + hand * 42;
    const float* cw = hand ? rcw : lcw;
    const float* cb = hand ? rcb : lcb;

    __shared__ float xs[42];
    __shared__ float z[16 * 20];
    const int tid = threadIdx.x;
    if (tid < 42) xs[tid] = x[tid];
    __syncthreads();

    for (int idx = tid; idx < 320; idx += 128) {
        int o = idx / 20, j = idx % 20;
        float v = cb[o]
                + cw[o * 4 + 0] * xs[2 * j]
                + cw[o * 4 + 1] * xs[2 * j + 2]
                + cw[o * 4 + 2] * xs[2 * j + 1]
                + cw[o * 4 + 3] * xs[2 * j + 3];
        z[o * 20 + j] = fmaxf(v, 0.f);
    }
    __syncthreads();

    for (int idx = tid; idx < FEAT; idx += 128) {
        int o = idx / 19, j = idx % 19;
        float v = fmaxf(z[o * 20 + j], z[o * 20 + j + 1]);
        split_pair(v, g_feath[(size_t)s * FEAT + idx], g_featl[(size_t)s * FEAT + idx]);
    }
}

// conv2(k=2,2->32) + relu + pool3 -> y pair; 2 blocks per sample (16 ch each)
__global__ __launch_bounds__(256)
void conv2pool_kernel(const float* __restrict__ w2, const float* __restrict__ b2)
{
    __shared__ float slo[HF], sro[HF], sw[128], sb[32];
    const int n    = blockIdx.x;
    const int half = blockIdx.y;
    const int tid  = threadIdx.x;
    const int wid  = tid >> 5;
    const int lane = tid & 31;
    for (int i = tid; i < HF; i += 256) {
        slo[i] = g_both[(size_t)n * HF + i];
        sro[i] = g_both[(size_t)(NB + n) * HF + i];
    }
    if (tid < 128) sw[tid] = w2[tid];
    if (tid < 32)  sb[tid] = b2[tid];
    __syncthreads();

    #pragma unroll
    for (int oo = 0; oo < 2; ++oo) {
        const int o = half * 16 + oo * 8 + wid;
        const float w00 = sw[o * 4 + 0], w01 = sw[o * 4 + 1];
        const float w10 = sw[o * 4 + 2], w11 = sw[o * 4 + 3];
        const float bb = sb[o];
        const size_t obase = (size_t)n * YK + o * 297;
        for (int jj = lane; jj < 297; jj += 32) {
            float l0 = slo[jj], l1 = slo[jj + 1], l2v = slo[jj + 2], l3 = slo[jj + 3];
            float r0 = sro[jj], r1 = sro[jj + 1], r2v = sro[jj + 2], r3 = sro[jj + 3];
            float z0 = bb + w00 * l0  + w01 * l1  + w10 * r0  + w11 * r1;
            float z1 = bb + w00 * l1  + w01 * l2v + w10 * r1  + w11 * r2v;
            float z2 = bb + w00 * l2v + w01 * l3  + w10 * r2v + w11 * r3;
            float v = fmaxf(fmaxf(z0, z1), fmaxf(z2, 0.f));
            split_pair(v, g_yh[obase + jj], g_yl[obase + jj]);
        }
    }
}

// final: hidden = sum(hpart); i2h = sum(part)+l2b; out = relu((i2h+hidden)@ow^T+ob)
__global__ __launch_bounds__(512)
void out_kernel(const float* __restrict__ part,
                const float* __restrict__ hpart,
                const float* __restrict__ l2b,
                const float* __restrict__ ow,
                const float* __restrict__ ob,
                float* __restrict__ out,
                float* __restrict__ hidOut)
{
    __shared__ float val[HID];
    const int n   = blockIdx.x;
    const int tid = threadIdx.x;

    if (tid < HID) {
        const size_t o = (size_t)n * HID + tid;
        float hs = hpart[o];
        #pragma unroll
        for (int s = 1; s < CHS; ++s) hs += hpart[(size_t)s * NB * HID + o];
        float is = l2b[tid];
        #pragma unroll
        for (int s = 0; s < L2S; ++s) is += part[(size_t)s * NB * HID + o];
        hidOut[o] = hs;
        val[tid] = hs + is;
    }
    __syncthreads();

    if (tid < OUT * 32) {
        const int m    = tid >> 5;
        const int lane = tid & 31;
        const float* w = ow + (size_t)m * HID;
        float s = 0.f;
        for (int k = lane; k < HID; k += 32) s += val[k] * w[k];
        #pragma unroll
        for (int o = 16; o; o >>= 1) s += __shfl_down_sync(0xffffffffu, s, o);
        if (lane == 0) out[n * OUT + m] = fmaxf(s + ob[m], 0.f);
    }
}

// ---------------------------------------------------------------------------
static cudaStream_t s_side = nullptr;
static cudaEvent_t  s_evF  = nullptr;
static cudaEvent_t  s_evJ  = nullptr;

extern "C" void kernel_launch(void* const* d_in, const int* in_sizes, int n_in,
                              void* d_out, int out_size)
{
    if (!s_side) {
        cudaStreamCreateWithFlags(&s_side, cudaStreamNonBlocking);
        cudaEventCreateWithFlags(&s_evF, cudaEventDisableTiming);
        cudaEventCreateWithFlags(&s_evJ, cudaEventDisableTiming);
    }

    const float* hand_data = (const float*)d_in[0];
    const float* hidden    = (const float*)d_in[1];
    const float* l_conv_w  = (const float*)d_in[2];
    const float* l_conv_b  = (const float*)d_in[3];
    const float* l_fc_w    = (const float*)d_in[4];
    const float* l_fc_b    = (const float*)d_in[5];
    const float* r_conv_w  = (const float*)d_in[6];
    const float* r_conv_b  = (const float*)d_in[7];
    const float* r_fc_w    = (const float*)d_in[8];
    const float* r_fc_b    = (const float*)d_in[9];
    const float* conv2_w   = (const float*)d_in[10];
    const float* conv2_b   = (const float*)d_in[11];
    const float* l2_w      = (const float*)d_in[12];
    const float* l2_b      = (const float*)d_in[13];
    const float* h2h_w     = (const float*)d_in[14];
    const float* h2h_b     = (const float*)d_in[15];
    const float* out_w     = (const float*)d_in[16];
    const float* out_b     = (const float*)d_in[17];

    const int T    = in_sizes[0] / (NB * 84);
    const int tOff = (T - 1) * NB * 84;

    bf *feath, *featl, *yh, *yl;
    bf *Wh, *Wl, *WTh, *WTl, *M0h, *M0l, *M0Th, *M0Tl, *M1h, *M1l, *M1Th, *M1Tl;
    bf *h0h, *h0l;
    float *both, *part, *cpart, *hpart, *hid;
    cudaGetSymbolAddress((void**)&feath, g_feath);
    cudaGetSymbolAddress((void**)&featl, g_featl);
    cudaGetSymbolAddress((void**)&both,  g_both);
    cudaGetSymbolAddress((void**)&yh,    g_yh);
    cudaGetSymbolAddress((void**)&yl,    g_yl);
    cudaGetSymbolAddress((void**)&part,  g_part);
    cudaGetSymbolAddress((void**)&cpart, g_cpart);
    cudaGetSymbolAddress((void**)&hpart, g_hpart);
    cudaGetSymbolAddress((void**)&Wh,    g_Wh);
    cudaGetSymbolAddress((void**)&Wl,    g_Wl);
    cudaGetSymbolAddress((void**)&WTh,   g_WTh);
    cudaGetSymbolAddress((void**)&WTl,   g_WTl);
    cudaGetSymbolAddress((void**)&M0h,   g_M0h);
    cudaGetSymbolAddress((void**)&M0l,   g_M0l);
    cudaGetSymbolAddress((void**)&M0Th,  g_M0Th);
    cudaGetSymbolAddress((void**)&M0Tl,  g_M0Tl);
    cudaGetSymbolAddress((void**)&M1h,   g_M1h);
    cudaGetSymbolAddress((void**)&M1l,   g_M1l);
    cudaGetSymbolAddress((void**)&M1Th,  g_M1Th);
    cudaGetSymbolAddress((void**)&M1Tl,  g_M1Tl);
    cudaGetSymbolAddress((void**)&h0h,   g_h0h);
    cudaGetSymbolAddress((void**)&h0l,   g_h0l);
    cudaGetSymbolAddress((void**)&hid,   g_hid);

    float* hidOut = (out_size >= NB * OUT + NB * HID) ? ((float*)d_out) + NB * OUT : hid;

    // fork side stream off the main stream head
    cudaEventRecord(s_evF, 0);
    cudaStreamWaitEvent(s_side, s_evF, 0);

    // ---- side stream: pad -> 5x (split-K squaring + reduce) -> hidden partials
    pad_kernel<<<(HIDP * HIDP + 255) / 256, 256, 0, s_side>>>(h2h_w, h2h_b, hidden);
    {
        const bf *sh = Wh, *sl = Wl, *sth = WTh, *stl = WTl;
        bf* dh [5] = { M0h,  M1h,  M0h,  M1h,  M0h  };
        bf* dl [5] = { M0l,  M1l,  M0l,  M1l,  M0l  };
        bf* dth[5] = { M0Th, M1Th, M0Th, M1Th, M0Th };
        bf* dtl[5] = { M0Tl, M1Tl, M0Tl, M1Tl, M0Tl };
        for (int i = 0; i < 5; ++i) {
            pp_gemm<<<dim3(8, 8, CHS), 256, 0, s_side>>>(
                HIDP, HIDP, HIDP, sh, sl, HIDP, sth, stl, HIDP, cpart, HIDP, CHLEN);
            if (i < 4)
                reduce_split<true><<<dim3(16, 16), 256, 0, s_side>>>(
                    cpart, dh[i], dl[i], dth[i], dtl[i]);
            else
                reduce_split<false><<<dim3(16, 16), 256, 0, s_side>>>(
                    cpart, dh[i], dl[i], nullptr, nullptr);
            sh = dh[i]; sl = dl[i]; sth = dth[i]; stl = dtl[i];
        }
        // hidden partials = h0aug @ M32^T (bias via homogeneous column)
        pp_gemm<<<dim3(8, 8, CHS), 256, 0, s_side>>>(
            NB, HID, HIDP, h0h, h0l, HIDP, M0h, M0l, HIDP, hpart, HID, CHLEN);
    }
    cudaEventRecord(s_evJ, s_side);

    // ---- main stream: data front-end
    hand_feat_kernel<<<1024, 128>>>(hand_data, l_conv_w, l_conv_b, r_conv_w, r_conv_b, tOff);
    fc_gemm<<<dim3(5, 16), 256>>>(feath, featl, l_fc_w, l_fc_b, r_fc_w, r_fc_b, both);
    conv2pool_kernel<<<dim3(NB, 2), 256>>>(conv2_w, conv2_b);
    l2_gemm<<<dim3(8, 8, L2S), 256>>>(yh, yl, l2_w, part);

    // ---- join + final fused kernel
    cudaStreamWaitEvent(0, s_evJ, 0);
    out_kernel<<<NB, 512>>>(part, hpart, l2_b, out_w, out_b, (float*)d_out, hidOut);
}